// round 1
// baseline (speedup 1.0000x reference)
#include <cuda_runtime.h>
#include <math.h>

#define L     4096
#define CCH   128
#define DI    256
#define NDIR  3
#define LT    (NDIR*L)      // 12288
#define DS    16
#define DR    8
#define NCHUNK 64
#define CHLEN  64

// ---------------- scratch (device globals; no allocation) ----------------
__device__ float g_tok[L*CCH];        // LN2(LN1(x)) tokens, [s][c]
__device__ float g_xz[L*2*DI];        // in_proj output per token, [s][512]
__device__ float g_xc[LT*DI];         // conv+silu, [dir*L+l][256]
__device__ float g_dbl[LT*40];        // x_dbl: dt(8), B(16), C(16)
__device__ float g_delta[LT*DI];      // softplus(dt@dtw+b)
__device__ float g_y[LT*DI];          // gated scan output
__device__ float g_mo[LT*CCH];        // out_proj result (reused for fc2 out)
__device__ float g_res[CCH*L];        // out_res, channel-major
__device__ float g_hid[L*512];        // fc1 output
__device__ float g_P [NDIR*DI*NCHUNK*DS];
__device__ float g_S [NDIR*DI*NCHUNK*DS];
__device__ float g_h0[NDIR*DI*NCHUNK*DS];

// sequence position l (of direction dir) -> token index s
__device__ __forceinline__ int ptok(int dir, int l){
    int a = l >> 8, b = (l >> 4) & 15, c = l & 15;
    if (dir == 0) return l;                  // l=(d,h,w)
    if (dir == 1) return c*256 + a*16 + b;   // l=(h,w,d) -> s=(d,h,w)
    return b*256 + c*16 + a;                 // l=(w,d,h) -> s=(d,h,w)
}

__device__ __forceinline__ float bsum128(float v, float* sh){
    #pragma unroll
    for (int o = 16; o; o >>= 1) v += __shfl_xor_sync(0xffffffffu, v, o);
    __syncthreads();
    if ((threadIdx.x & 31) == 0) sh[threadIdx.x >> 5] = v;
    __syncthreads();
    return sh[0] + sh[1] + sh[2] + sh[3];
}

// ---------------- K1: double token LayerNorm ----------------
__global__ void k_ln_tok(const float* __restrict__ x,
                         const float* __restrict__ lnw, const float* __restrict__ lnb,
                         const float* __restrict__ mw,  const float* __restrict__ mb){
    __shared__ float sh[4];
    int s = blockIdx.x, c = threadIdx.x;
    float v   = x[c*L + s];
    float m   = bsum128(v, sh) * (1.f/128.f);
    float d   = v - m;
    float var = bsum128(d*d, sh) * (1.f/128.f);
    float v1  = d * rsqrtf(var + 1e-6f) * lnw[c] + lnb[c];
    float m2  = bsum128(v1, sh) * (1.f/128.f);
    float d2  = v1 - m2;
    float v2  = bsum128(d2*d2, sh) * (1.f/128.f);
    g_tok[s*CCH + c] = d2 * rsqrtf(v2 + 1e-5f) * mw[c] + mb[c];
}

// ---------------- generic token-block GEMM: out[m][n] = act(A[m]·W[n] + bias) ----------------
// ACT: 0 none, 1 silu, 2 gelu(exact), 3 softplus
template<int K, int TT, int ACT, bool BIAS>
__global__ void k_gemm(const float* __restrict__ A, int lda,
                       const float* __restrict__ W,
                       const float* __restrict__ bias,
                       float* __restrict__ out, int N){
    __shared__ float sA[TT][K];
    int m0 = blockIdx.x * TT;
    for (int idx = threadIdx.x; idx < TT*K; idx += blockDim.x){
        int t = idx / K, k = idx % K;
        sA[t][k] = A[(m0 + t)*lda + k];
    }
    __syncthreads();
    for (int n = threadIdx.x; n < N; n += blockDim.x){
        float acc[TT];
        #pragma unroll
        for (int t = 0; t < TT; t++) acc[t] = BIAS ? bias[n] : 0.f;
        const float* w = W + (size_t)n * K;
        for (int k = 0; k < K; k++){
            float wv = w[k];
            #pragma unroll
            for (int t = 0; t < TT; t++) acc[t] += wv * sA[t][k];
        }
        #pragma unroll
        for (int t = 0; t < TT; t++){
            float v = acc[t];
            if (ACT == 1)      v = v / (1.f + __expf(-v));
            else if (ACT == 2) v = 0.5f * v * (1.f + erff(v * 0.70710678118654752f));
            else if (ACT == 3) v = (v > 20.f) ? v : log1pf(__expf(v));
            out[(size_t)(m0 + t)*N + n] = v;
        }
    }
}

// ---------------- K3: causal depthwise conv (k=4) + silu, per direction ----------------
__global__ void k_conv(const float* __restrict__ cw, const float* __restrict__ cb){
    int dir = blockIdx.y, l = blockIdx.x, ch = threadIdx.x;
    float acc = cb[ch];
    #pragma unroll
    for (int k = 0; k < 4; k++){
        int lp = l - 3 + k;
        if (lp >= 0) acc += cw[ch*4 + k] * g_xz[ptok(dir, lp)*(2*DI) + ch];
    }
    acc = acc / (1.f + __expf(-acc));
    g_xc[(size_t)(dir*L + l)*DI + ch] = acc;
}

// ---------------- scan pass A: chunk summaries (P, S) ----------------
__global__ void k_scanA(const float* __restrict__ Alog){
    int g = blockIdx.x*16 + (threadIdx.x >> 4);   // group over 3*256*64
    int n = threadIdx.x & 15;
    int chunk = g & 63;
    int d     = (g >> 6) & 255;
    int dir   = g >> 14;
    float Av = -__expf(Alog[d*DS + n]);
    float P = 1.f, S = 0.f;
    int base = dir*L + chunk*CHLEN;
    for (int st = 0; st < CHLEN; st++){
        int lg = base + st;
        float dl = g_delta[(size_t)lg*DI + d];
        float u  = g_xc  [(size_t)lg*DI + d];
        float Bv = g_dbl [(size_t)lg*40 + 8 + n];
        float a  = __expf(dl * Av);
        P *= a;
        S = a*S + dl*Bv*u;
    }
    g_P[(size_t)g*DS + n] = P;
    g_S[(size_t)g*DS + n] = S;
}

// ---------------- scan pass B: inter-chunk sequential combine ----------------
__global__ void k_scanB(){
    int i = blockIdx.x*blockDim.x + threadIdx.x;   // 3*256*16 = 12288
    if (i >= NDIR*DI*DS) return;
    int n = i & 15;
    int d = (i >> 4) & 255;
    int dir = i >> 12;
    float h = 0.f;
    for (int c = 0; c < NCHUNK; c++){
        size_t g = ((size_t)(dir*DI + d))*NCHUNK + c;
        g_h0[g*DS + n] = h;
        h = g_P[g*DS + n]*h + g_S[g*DS + n];
    }
}

// ---------------- scan pass C: recompute + C-dot + D skip + silu(z) gate ----------------
__global__ void k_scanC(const float* __restrict__ Alog, const float* __restrict__ Dp){
    int g = blockIdx.x*16 + (threadIdx.x >> 4);
    int n = threadIdx.x & 15;
    int chunk = g & 63;
    int d     = (g >> 6) & 255;
    int dir   = g >> 14;
    float Av = -__expf(Alog[d*DS + n]);
    float h  = g_h0[(size_t)g*DS + n];
    float Dv = Dp[d];
    int base = dir*L + chunk*CHLEN;
    for (int st = 0; st < CHLEN; st++){
        int lg = base + st;
        float dl = g_delta[(size_t)lg*DI + d];
        float u  = g_xc  [(size_t)lg*DI + d];
        float Bv = g_dbl [(size_t)lg*40 + 8 + n];
        float Cv = g_dbl [(size_t)lg*40 + 24 + n];
        float a  = __expf(dl * Av);
        h = a*h + dl*Bv*u;
        float p = h * Cv;
        p += __shfl_xor_sync(0xffffffffu, p, 8);
        p += __shfl_xor_sync(0xffffffffu, p, 4);
        p += __shfl_xor_sync(0xffffffffu, p, 2);
        p += __shfl_xor_sync(0xffffffffu, p, 1);
        if (n == 0){
            int l = lg - dir*L;
            float z = g_xz[ptok(dir, l)*(2*DI) + DI + d];
            float yy = (p + u*Dv) * (z / (1.f + __expf(-z)));
            g_y[(size_t)lg*DI + d] = yy;
        }
    }
}

// ---------------- K8: 3-dir gather + proj(384->128) + residual ----------------
__global__ void k_proj(const float* __restrict__ pw, const float* __restrict__ pb,
                       const float* __restrict__ x){
    __shared__ float sc[8][3*CCH];
    int s0 = blockIdx.x * 8;
    for (int idx = threadIdx.x; idx < 8*3*CCH; idx += blockDim.x){
        int t = idx / (3*CCH); int k = idx % (3*CCH);
        int dir = k / CCH, c = k % CCH;
        int s = s0 + t;
        int a = s >> 8, b = (s >> 4) & 15, cc = s & 15;  // s=(d,h,w)=(a,b,cc)
        int l;
        if (dir == 0)      l = s;
        else if (dir == 1) l = b*256 + cc*16 + a;        // l=(h,w,d)
        else               l = cc*256 + a*16 + b;        // l=(w,d,h)
        sc[t][k] = g_mo[(size_t)(dir*L + l)*CCH + c];
    }
    __syncthreads();
    int o = threadIdx.x;
    float acc[8];
    #pragma unroll
    for (int t = 0; t < 8; t++) acc[t] = pb[o];
    for (int k = 0; k < 3*CCH; k++){
        float w = pw[o*(3*CCH) + k];
        #pragma unroll
        for (int t = 0; t < 8; t++) acc[t] += w * sc[t][k];
    }
    #pragma unroll
    for (int t = 0; t < 8; t++){
        int s = s0 + t;
        g_res[o*L + s] = x[o*L + s] + acc[t];
    }
}

// ---------------- K9: LN over channels of out_res -> g_tok ----------------
__global__ void k_ln_res(const float* __restrict__ lnw, const float* __restrict__ lnb){
    __shared__ float sh[4];
    int s = blockIdx.x, c = threadIdx.x;
    float v   = g_res[c*L + s];
    float m   = bsum128(v, sh) * (1.f/128.f);
    float d   = v - m;
    float var = bsum128(d*d, sh) * (1.f/128.f);
    g_tok[s*CCH + c] = d * rsqrtf(var + 1e-6f) * lnw[c] + lnb[c];
}

// ---------------- K11: final residual add + layout transpose ----------------
__global__ void k_final(float* __restrict__ out){
    int i = blockIdx.x*blockDim.x + threadIdx.x;   // over 128*4096
    int o = i / L, s = i % L;
    out[i] = g_res[i] + g_mo[(size_t)s*CCH + o];
}

// ---------------- launch ----------------
extern "C" void kernel_launch(void* const* d_in, const int* in_sizes, int n_in,
                              void* d_out, int out_size){
    const float* x        = (const float*)d_in[0];
    const float* ln_w     = (const float*)d_in[1];
    const float* ln_b     = (const float*)d_in[2];
    const float* mnorm_w  = (const float*)d_in[3];
    const float* mnorm_b  = (const float*)d_in[4];
    const float* in_proj  = (const float*)d_in[5];
    const float* conv_w   = (const float*)d_in[6];
    const float* conv_b   = (const float*)d_in[7];
    const float* x_proj   = (const float*)d_in[8];
    const float* dt_proj  = (const float*)d_in[9];
    const float* dt_bias  = (const float*)d_in[10];
    const float* A_log    = (const float*)d_in[11];
    const float* D_param  = (const float*)d_in[12];
    const float* out_proj = (const float*)d_in[13];
    const float* proj_w   = (const float*)d_in[14];
    const float* proj_b   = (const float*)d_in[15];
    const float* fc1_w    = (const float*)d_in[16];
    const float* fc1_b    = (const float*)d_in[17];
    const float* fc2_w    = (const float*)d_in[18];
    const float* fc2_b    = (const float*)d_in[19];
    float* out = (float*)d_out;

    void *p_tok, *p_xz, *p_xc, *p_dbl, *p_delta, *p_y, *p_mo, *p_hid;
    cudaGetSymbolAddress(&p_tok,   g_tok);
    cudaGetSymbolAddress(&p_xz,    g_xz);
    cudaGetSymbolAddress(&p_xc,    g_xc);
    cudaGetSymbolAddress(&p_dbl,   g_dbl);
    cudaGetSymbolAddress(&p_delta, g_delta);
    cudaGetSymbolAddress(&p_y,     g_y);
    cudaGetSymbolAddress(&p_mo,    g_mo);
    cudaGetSymbolAddress(&p_hid,   g_hid);

    // 1. token double-LN (shared across all 3 directions)
    k_ln_tok<<<L, 128>>>(x, ln_w, ln_b, mnorm_w, mnorm_b);
    // 2. in_proj: [4096,128] @ [512,128]^T  (computed once, shared by all dirs)
    k_gemm<128,8,0,false><<<L/8, 256>>>((const float*)p_tok, 128, in_proj, nullptr, (float*)p_xz, 512);
    // 3. causal conv + silu, per direction sequence order
    k_conv<<<dim3(L, NDIR), DI>>>(conv_w, conv_b);
    // 4. x_dbl: [12288,256] @ [40,256]^T
    k_gemm<256,8,0,false><<<LT/8, 256>>>((const float*)p_xc, 256, x_proj, nullptr, (float*)p_dbl, 40);
    // 5. delta: softplus(dt @ [256,8]^T + b)
    k_gemm<8,8,3,true><<<LT/8, 256>>>((const float*)p_dbl, 40, dt_proj, dt_bias, (float*)p_delta, 256);
    // 6-8. chunked selective scan
    k_scanA<<<NDIR*DI*NCHUNK/16, 256>>>(A_log);
    k_scanB<<<(NDIR*DI*DS + 255)/256, 256>>>();
    k_scanC<<<NDIR*DI*NCHUNK/16, 256>>>(A_log, D_param);
    // 9. out_proj: [12288,256] @ [128,256]^T
    k_gemm<256,8,0,false><<<LT/8, 256>>>((const float*)p_y, 256, out_proj, nullptr, (float*)p_mo, 128);
    // 10. gather 3 dirs + proj(384->128) + residual -> g_res
    k_proj<<<L/8, 128>>>(proj_w, proj_b, x);
    // 11. LN(out_res) -> g_tok
    k_ln_res<<<L, 128>>>(ln_w, ln_b);
    // 12. fc1 + exact GELU
    k_gemm<128,8,2,true><<<L/8, 256>>>((const float*)p_tok, 128, fc1_w, fc1_b, (float*)p_hid, 512);
    // 13. fc2 (token-major into g_mo)
    k_gemm<512,8,0,true><<<L/8, 256>>>((const float*)p_hid, 512, fc2_w, fc2_b, (float*)p_mo, 128);
    // 14. final residual + transpose to (C, D, H, W)
    k_final<<<(CCH*L)/256, 256>>>(out);
}

// round 2
// speedup vs baseline: 2.8182x; 2.8182x over previous
#include <cuda_runtime.h>
#include <math.h>

#define L     4096
#define CCH   128
#define DI    256
#define NDIR  3
#define LT    (NDIR*L)      // 12288
#define DS    16
#define NCHUNK 64
#define CHLEN  64

// ---------------- scratch (device globals; no allocation) ----------------
__device__ float g_xT[L*CCH];         // x transposed: [s][c]
__device__ float g_tok[L*CCH];        // LN2(LN1(x)) tokens, [s][c]
__device__ float g_xz[L*2*DI];        // in_proj output per token, [s][512]
__device__ float g_xc[LT*DI];         // conv+silu, [dir*L+l][256]
__device__ float g_dbl[LT*40];        // x_dbl: dt(8), B(16), C(16)
__device__ float g_delta[LT*DI];      // softplus(dt@dtw+b)
__device__ float g_y[LT*DI];          // gated scan output
__device__ float g_mo[LT*CCH];        // out_proj result
__device__ float g_cat[L*3*CCH];      // gathered 3-dir concat, [s][384]
__device__ float g_resT[L*CCH];       // out_res, token-major [s][c]
__device__ float g_hid[L*512];        // fc1 output
__device__ float g_P [NDIR*DI*NCHUNK*DS];
__device__ float g_S [NDIR*DI*NCHUNK*DS];
__device__ float g_h0[NDIR*DI*NCHUNK*DS];

// sequence position l (of direction dir) -> token index s
__device__ __forceinline__ int ptok(int dir, int l){
    int a = l >> 8, b = (l >> 4) & 15, c = l & 15;
    if (dir == 0) return l;                  // l=(d,h,w)
    if (dir == 1) return c*256 + a*16 + b;   // l=(h,w,d) -> s=(d,h,w)
    return b*256 + c*16 + a;                 // l=(w,d,h) -> s=(d,h,w)
}

__device__ __forceinline__ float bsum128(float v, float* sh){
    #pragma unroll
    for (int o = 16; o; o >>= 1) v += __shfl_xor_sync(0xffffffffu, v, o);
    __syncthreads();
    if ((threadIdx.x & 31) == 0) sh[threadIdx.x >> 5] = v;
    __syncthreads();
    return sh[0] + sh[1] + sh[2] + sh[3];
}

// ---------------- K0: transpose x[c][s] -> xT[s][c] ----------------
__global__ void k_xpose(const float* __restrict__ x){
    __shared__ float t[32][33];
    int bs = blockIdx.x*32, bc = blockIdx.y*32;
    int tx = threadIdx.x & 31, ty = threadIdx.x >> 5;   // 8 warps
    #pragma unroll
    for (int r = ty; r < 32; r += 8)
        t[r][tx] = x[(size_t)(bc+r)*L + bs + tx];
    __syncthreads();
    #pragma unroll
    for (int r = ty; r < 32; r += 8)
        g_xT[(size_t)(bs+r)*CCH + bc + tx] = t[tx][r];
}

// ---------------- K1: double token LayerNorm (reads xT coalesced) ----------------
__global__ void k_ln_tok(const float* __restrict__ lnw, const float* __restrict__ lnb,
                         const float* __restrict__ mw,  const float* __restrict__ mb){
    __shared__ float sh[4];
    int s = blockIdx.x, c = threadIdx.x;
    float v   = g_xT[(size_t)s*CCH + c];
    float m   = bsum128(v, sh) * (1.f/128.f);
    float d   = v - m;
    float var = bsum128(d*d, sh) * (1.f/128.f);
    float v1  = d * rsqrtf(var + 1e-6f) * lnw[c] + lnb[c];
    float m2  = bsum128(v1, sh) * (1.f/128.f);
    float d2  = v1 - m2;
    float v2  = bsum128(d2*d2, sh) * (1.f/128.f);
    g_tok[(size_t)s*CCH + c] = d2 * rsqrtf(v2 + 1e-5f) * mw[c] + mb[c];
}

// ---------------- tiled SGEMM: out[m][n] = act(A[m][:K] . W[n][:K] + bias[n]) ----------------
// TM in {64,128}, TN=64, K multiple of 16. ACT: 0 none,1 silu,2 gelu,3 softplus.
// RES: add res[m*N+n].  TSTORE: store transposed out[n*L+m] instead of out[m*N+n].
template<int TM, int ACT, bool BIAS, bool RES, bool TSTORE>
__global__ void k_tgemm(const float* __restrict__ A,
                        const float* __restrict__ W,
                        const float* __restrict__ bias,
                        const float* __restrict__ res,
                        float* __restrict__ out,
                        int N, int K){
    constexpr int TN = 64, KS = 16;
    constexpr int RM = TM/16;                 // 4 or 8 rows per thread
    __shared__ float As[KS][TM+4];
    __shared__ float Bs[KS][TN+4];
    int tid = threadIdx.x;
    int tx = tid & 15, ty = tid >> 4;
    int m0 = blockIdx.x * TM, n0 = blockIdx.y * TN;
    float acc[RM][4];
    #pragma unroll
    for (int i = 0; i < RM; i++)
        #pragma unroll
        for (int j = 0; j < 4; j++) acc[i][j] = 0.f;

    int lkq = tid & 3, lm = tid >> 2;         // loader coords: lm in 0..63
    for (int k0 = 0; k0 < K; k0 += KS){
        #pragma unroll
        for (int h = 0; h < TM/64; h++){
            int m = lm + h*64;
            float4 v = *(const float4*)(A + (size_t)(m0+m)*K + k0 + lkq*4);
            As[lkq*4+0][m] = v.x; As[lkq*4+1][m] = v.y;
            As[lkq*4+2][m] = v.z; As[lkq*4+3][m] = v.w;
        }
        {
            int n = n0 + lm;
            float4 v = make_float4(0.f,0.f,0.f,0.f);
            if (n < N) v = *(const float4*)(W + (size_t)n*K + k0 + lkq*4);
            Bs[lkq*4+0][lm] = v.x; Bs[lkq*4+1][lm] = v.y;
            Bs[lkq*4+2][lm] = v.z; Bs[lkq*4+3][lm] = v.w;
        }
        __syncthreads();
        #pragma unroll
        for (int kk = 0; kk < KS; kk++){
            float4 b = *(const float4*)&Bs[kk][tx*4];
            #pragma unroll
            for (int h = 0; h < TM/64; h++){
                float4 a = *(const float4*)&As[kk][h*64 + ty*4];
                acc[h*4+0][0] += a.x*b.x; acc[h*4+0][1] += a.x*b.y;
                acc[h*4+0][2] += a.x*b.z; acc[h*4+0][3] += a.x*b.w;
                acc[h*4+1][0] += a.y*b.x; acc[h*4+1][1] += a.y*b.y;
                acc[h*4+1][2] += a.y*b.z; acc[h*4+1][3] += a.y*b.w;
                acc[h*4+2][0] += a.z*b.x; acc[h*4+2][1] += a.z*b.y;
                acc[h*4+2][2] += a.z*b.z; acc[h*4+2][3] += a.z*b.w;
                acc[h*4+3][0] += a.w*b.x; acc[h*4+3][1] += a.w*b.y;
                acc[h*4+3][2] += a.w*b.z; acc[h*4+3][3] += a.w*b.w;
            }
        }
        __syncthreads();
    }
    #pragma unroll
    for (int h = 0; h < TM/64; h++)
        #pragma unroll
        for (int i = 0; i < 4; i++){
            int m = m0 + h*64 + ty*4 + i;
            #pragma unroll
            for (int j = 0; j < 4; j++){
                int n = n0 + tx*4 + j;
                if (n >= N) continue;
                float v = acc[h*4+i][j];
                if (BIAS) v += bias[n];
                if (ACT == 1)      v = v / (1.f + __expf(-v));
                else if (ACT == 2) v = 0.5f * v * (1.f + erff(v * 0.70710678118654752f));
                else if (ACT == 3) v = (v > 20.f) ? v : log1pf(__expf(v));
                if (RES) v += res[(size_t)m*N + n];
                if (TSTORE) out[(size_t)n*L + m] = v;
                else        out[(size_t)m*N + n] = v;
            }
        }
}

// ---------------- K3: causal depthwise conv (k=4) + silu, per direction ----------------
__global__ void k_conv(const float* __restrict__ cw, const float* __restrict__ cb){
    int dir = blockIdx.y, l = blockIdx.x, ch = threadIdx.x;
    float acc = cb[ch];
    #pragma unroll
    for (int k = 0; k < 4; k++){
        int lp = l - 3 + k;
        if (lp >= 0) acc += cw[ch*4 + k] * g_xz[(size_t)ptok(dir, lp)*(2*DI) + ch];
    }
    acc = acc / (1.f + __expf(-acc));
    g_xc[(size_t)(dir*L + l)*DI + ch] = acc;
}

// ---------------- K5: delta = softplus(dt @ dtw^T + b), K=8 ----------------
__global__ void k_delta(const float* __restrict__ dtw, const float* __restrict__ dtb){
    __shared__ float sdt[32][8];
    int lg0 = blockIdx.x*32;
    {
        int t = threadIdx.x >> 3, r = threadIdx.x & 7;
        sdt[t][r] = g_dbl[(size_t)(lg0+t)*40 + r];
    }
    __syncthreads();
    int n = threadIdx.x;
    float w[8];
    #pragma unroll
    for (int r = 0; r < 8; r++) w[r] = dtw[n*8 + r];
    float b = dtb[n];
    for (int tt = 0; tt < 32; tt++){
        float acc = b;
        #pragma unroll
        for (int r = 0; r < 8; r++) acc += w[r]*sdt[tt][r];
        acc = (acc > 20.f) ? acc : log1pf(__expf(acc));
        g_delta[(size_t)(lg0+tt)*DI + n] = acc;
    }
}

// ---------------- scan pass A: chunk summaries (P, S) ----------------
__global__ void k_scanA(const float* __restrict__ Alog){
    int g = blockIdx.x*16 + (threadIdx.x >> 4);
    int n = threadIdx.x & 15;
    int chunk = g & 63;
    int d     = (g >> 6) & 255;
    int dir   = g >> 14;
    float Av = -__expf(Alog[d*DS + n]);
    float P = 1.f, S = 0.f;
    int base = dir*L + chunk*CHLEN;
    for (int st = 0; st < CHLEN; st++){
        int lg = base + st;
        float dl = g_delta[(size_t)lg*DI + d];
        float u  = g_xc  [(size_t)lg*DI + d];
        float Bv = g_dbl [(size_t)lg*40 + 8 + n];
        float a  = __expf(dl * Av);
        P *= a;
        S = a*S + dl*Bv*u;
    }
    g_P[(size_t)g*DS + n] = P;
    g_S[(size_t)g*DS + n] = S;
}

// ---------------- scan pass B: inter-chunk sequential combine ----------------
__global__ void k_scanB(){
    int i = blockIdx.x*blockDim.x + threadIdx.x;
    if (i >= NDIR*DI*DS) return;
    int n = i & 15;
    int d = (i >> 4) & 255;
    int dir = i >> 12;
    float h = 0.f;
    for (int c = 0; c < NCHUNK; c++){
        size_t g = ((size_t)(dir*DI + d))*NCHUNK + c;
        g_h0[g*DS + n] = h;
        h = g_P[g*DS + n]*h + g_S[g*DS + n];
    }
}

// ---------------- scan pass C: recompute + C-dot + D skip + silu(z) gate ----------------
__global__ void k_scanC(const float* __restrict__ Alog, const float* __restrict__ Dp){
    int g = blockIdx.x*16 + (threadIdx.x >> 4);
    int n = threadIdx.x & 15;
    int chunk = g & 63;
    int d     = (g >> 6) & 255;
    int dir   = g >> 14;
    float Av = -__expf(Alog[d*DS + n]);
    float h  = g_h0[(size_t)g*DS + n];
    float Dv = Dp[d];
    int base = dir*L + chunk*CHLEN;
    for (int st = 0; st < CHLEN; st++){
        int lg = base + st;
        float dl = g_delta[(size_t)lg*DI + d];
        float u  = g_xc  [(size_t)lg*DI + d];
        float Bv = g_dbl [(size_t)lg*40 + 8 + n];
        float Cv = g_dbl [(size_t)lg*40 + 24 + n];
        float a  = __expf(dl * Av);
        h = a*h + dl*Bv*u;
        float p = h * Cv;
        p += __shfl_xor_sync(0xffffffffu, p, 8);
        p += __shfl_xor_sync(0xffffffffu, p, 4);
        p += __shfl_xor_sync(0xffffffffu, p, 2);
        p += __shfl_xor_sync(0xffffffffu, p, 1);
        if (n == 0){
            int l = lg - dir*L;
            float z = g_xz[(size_t)ptok(dir, l)*(2*DI) + DI + d];
            float yy = (p + u*Dv) * (z / (1.f + __expf(-z)));
            g_y[(size_t)lg*DI + d] = yy;
        }
    }
}

// ---------------- K9: gather 3 directions into cat [s][384] ----------------
__global__ void k_gather(){
    int s = blockIdx.x;
    int t = threadIdx.x;           // 0..383
    int dir = t >> 7, c = t & 127;
    int a = s >> 8, b = (s >> 4) & 15, cc = s & 15;   // s=(d,h,w)
    int l = (dir == 0) ? s : (dir == 1 ? b*256 + cc*16 + a : cc*256 + a*16 + b);
    g_cat[(size_t)s*(3*CCH) + t] = g_mo[(size_t)(dir*L + l)*CCH + c];
}

// ---------------- K11: LN over channels of out_res (token-major) -> g_tok ----------------
__global__ void k_ln_res(const float* __restrict__ lnw, const float* __restrict__ lnb){
    __shared__ float sh[4];
    int s = blockIdx.x, c = threadIdx.x;
    float v   = g_resT[(size_t)s*CCH + c];
    float m   = bsum128(v, sh) * (1.f/128.f);
    float d   = v - m;
    float var = bsum128(d*d, sh) * (1.f/128.f);
    g_tok[(size_t)s*CCH + c] = d * rsqrtf(var + 1e-6f) * lnw[c] + lnb[c];
}

// ---------------- launch ----------------
extern "C" void kernel_launch(void* const* d_in, const int* in_sizes, int n_in,
                              void* d_out, int out_size){
    const float* x        = (const float*)d_in[0];
    const float* ln_w     = (const float*)d_in[1];
    const float* ln_b     = (const float*)d_in[2];
    const float* mnorm_w  = (const float*)d_in[3];
    const float* mnorm_b  = (const float*)d_in[4];
    const float* in_proj  = (const float*)d_in[5];
    const float* conv_w   = (const float*)d_in[6];
    const float* conv_b   = (const float*)d_in[7];
    const float* x_proj   = (const float*)d_in[8];
    const float* dt_proj  = (const float*)d_in[9];
    const float* dt_bias  = (const float*)d_in[10];
    const float* A_log    = (const float*)d_in[11];
    const float* D_param  = (const float*)d_in[12];
    const float* out_proj = (const float*)d_in[13];
    const float* proj_w   = (const float*)d_in[14];
    const float* proj_b   = (const float*)d_in[15];
    const float* fc1_w    = (const float*)d_in[16];
    const float* fc1_b    = (const float*)d_in[17];
    const float* fc2_w    = (const float*)d_in[18];
    const float* fc2_b    = (const float*)d_in[19];
    float* out = (float*)d_out;

    void *p_tok, *p_xz, *p_xc, *p_dbl, *p_y, *p_mo, *p_cat, *p_resT, *p_hid, *p_xT;
    cudaGetSymbolAddress(&p_tok,  g_tok);
    cudaGetSymbolAddress(&p_xz,   g_xz);
    cudaGetSymbolAddress(&p_xc,   g_xc);
    cudaGetSymbolAddress(&p_dbl,  g_dbl);
    cudaGetSymbolAddress(&p_y,    g_y);
    cudaGetSymbolAddress(&p_mo,   g_mo);
    cudaGetSymbolAddress(&p_cat,  g_cat);
    cudaGetSymbolAddress(&p_resT, g_resT);
    cudaGetSymbolAddress(&p_hid,  g_hid);
    cudaGetSymbolAddress(&p_xT,   g_xT);

    // 0. transpose x -> xT
    k_xpose<<<dim3(L/32, CCH/32), 256>>>(x);
    // 1. token double-LN (shared across all 3 directions)
    k_ln_tok<<<L, 128>>>(ln_w, ln_b, mnorm_w, mnorm_b);
    // 2. in_proj: [4096,128] @ [512,128]^T
    k_tgemm<128,0,false,false,false><<<dim3(L/128, 512/64), 256>>>(
        (const float*)p_tok, in_proj, nullptr, nullptr, (float*)p_xz, 512, 128);
    // 3. causal conv + silu per direction
    k_conv<<<dim3(L, NDIR), DI>>>(conv_w, conv_b);
    // 4. x_dbl: [12288,256] @ [40,256]^T
    k_tgemm<64,0,false,false,false><<<dim3(LT/64, 1), 256>>>(
        (const float*)p_xc, x_proj, nullptr, nullptr, (float*)p_dbl, 40, 256);
    // 5. delta = softplus(dt @ dtw^T + b)
    k_delta<<<LT/32, 256>>>(dt_proj, dt_bias);
    // 6-8. chunked selective scan
    k_scanA<<<NDIR*DI*NCHUNK/16, 256>>>(A_log);
    k_scanB<<<(NDIR*DI*DS + 255)/256, 256>>>();
    k_scanC<<<NDIR*DI*NCHUNK/16, 256>>>(A_log, D_param);
    // 9. out_proj: [12288,256] @ [128,256]^T
    k_tgemm<128,0,false,false,false><<<dim3(LT/128, 2), 256>>>(
        (const float*)p_y, out_proj, nullptr, nullptr, (float*)p_mo, 128, 256);
    // 10. gather 3 dirs -> cat [s][384]
    k_gather<<<L, 3*CCH>>>();
    // 11. proj(384->128) + bias + x residual -> g_resT [s][c]
    k_tgemm<64,0,true,true,false><<<dim3(L/64, 2), 256>>>(
        (const float*)p_cat, proj_w, proj_b, (const float*)p_xT, (float*)p_resT, 128, 384);
    // 12. LN(out_res) -> g_tok
    k_ln_res<<<L, 128>>>(ln_w, ln_b);
    // 13. fc1 + exact GELU
    k_tgemm<128,2,true,false,false><<<dim3(L/128, 512/64), 256>>>(
        (const float*)p_tok, fc1_w, fc1_b, nullptr, (float*)p_hid, 512, 128);
    // 14. fc2 + bias + residual + transposed store directly to output (C,D,H,W)
    k_tgemm<64,0,true,true,true><<<dim3(L/64, 2), 256>>>(
        (const float*)p_hid, fc2_w, fc2_b, (const float*)p_resT, out, 128, 512);
}

// round 3
// speedup vs baseline: 3.0744x; 1.0909x over previous
#include <cuda_runtime.h>
#include <math.h>

#define L     4096
#define CCH   128
#define DI    256
#define NDIR  3
#define LT    (NDIR*L)
#define DS    16
#define NCHUNK 64
#define CHLEN  64
#define CTL   32

// ---------------- scratch ----------------
__device__ float g_xT[L*CCH];
__device__ float g_tok[L*CCH];
__device__ float g_xz[L*2*DI];
__device__ float g_xc[LT*DI];
__device__ float g_dbl[LT*40];
__device__ float g_delta[LT*DI];
__device__ float g_y[LT*DI];
__device__ float g_mo[LT*CCH];
__device__ float g_resT[L*CCH];
__device__ float g_hid[L*512];

typedef unsigned long long u64;

__device__ __forceinline__ void ffma2(u64 &d, u64 a, u64 b){
    asm("fma.rn.f32x2 %0, %1, %2, %0;" : "+l"(d) : "l"(a), "l"(b));
}
__device__ __forceinline__ u64 packdup(float v){
    u64 r; asm("mov.b64 %0, {%1, %1};" : "=l"(r) : "f"(v)); return r;
}
__device__ __forceinline__ void unpack2(u64 v, float &lo, float &hi){
    asm("mov.b64 {%0, %1}, %2;" : "=f"(lo), "=f"(hi) : "l"(v));
}

__device__ __forceinline__ int ptok(int dir, int l){
    int a = l >> 8, b = (l >> 4) & 15, c = l & 15;
    if (dir == 0) return l;
    if (dir == 1) return c*256 + a*16 + b;
    return b*256 + c*16 + a;
}
// token s -> sequence position l for direction dir (inverse gather)
__device__ __forceinline__ int stol(int dir, int s){
    int a = s >> 8, b = (s >> 4) & 15, cc = s & 15;
    if (dir == 0) return s;
    if (dir == 1) return b*256 + cc*16 + a;
    return cc*256 + a*16 + b;
}

// ---------------- K1: fused transpose + double LayerNorm ----------------
__global__ void k_lnx(const float* __restrict__ x,
                      const float* __restrict__ lnw, const float* __restrict__ lnb,
                      const float* __restrict__ mw,  const float* __restrict__ mb){
    __shared__ float t[128][33];
    int s0 = blockIdx.x*32;
    int lane = threadIdx.x & 31, w = threadIdx.x >> 5;
    for (int r = w; r < 128; r += 8)
        t[r][lane] = x[(size_t)r*L + s0 + lane];
    __syncthreads();
    for (int round = 0; round < 4; round++){
        int tloc = round*8 + w;
        int s = s0 + tloc;
        float v[4];
        #pragma unroll
        for (int i = 0; i < 4; i++) v[i] = t[lane + 32*i][tloc];
        #pragma unroll
        for (int i = 0; i < 4; i++) g_xT[(size_t)s*CCH + lane + 32*i] = v[i];
        float sum = v[0]+v[1]+v[2]+v[3];
        #pragma unroll
        for (int o = 16; o; o >>= 1) sum += __shfl_xor_sync(0xffffffffu, sum, o);
        float mean = sum * (1.f/128.f);
        float d[4], var = 0.f;
        #pragma unroll
        for (int i = 0; i < 4; i++){ d[i] = v[i]-mean; var += d[i]*d[i]; }
        #pragma unroll
        for (int o = 16; o; o >>= 1) var += __shfl_xor_sync(0xffffffffu, var, o);
        float rs = rsqrtf(var*(1.f/128.f) + 1e-6f);
        float v1[4];
        #pragma unroll
        for (int i = 0; i < 4; i++){
            int c = lane + 32*i;
            v1[i] = d[i]*rs*lnw[c] + lnb[c];
        }
        float sum2 = v1[0]+v1[1]+v1[2]+v1[3];
        #pragma unroll
        for (int o = 16; o; o >>= 1) sum2 += __shfl_xor_sync(0xffffffffu, sum2, o);
        float mean2 = sum2 * (1.f/128.f);
        float d2[4], var2 = 0.f;
        #pragma unroll
        for (int i = 0; i < 4; i++){ d2[i] = v1[i]-mean2; var2 += d2[i]*d2[i]; }
        #pragma unroll
        for (int o = 16; o; o >>= 1) var2 += __shfl_xor_sync(0xffffffffu, var2, o);
        float rs2 = rsqrtf(var2*(1.f/128.f) + 1e-5f);
        #pragma unroll
        for (int i = 0; i < 4; i++){
            int c = lane + 32*i;
            g_tok[(size_t)s*CCH + c] = d2[i]*rs2*mw[c] + mb[c];
        }
    }
}

// ---------------- f32x2 tiled SGEMM ----------------
// out[m][n] = act(A[m][:K] . W[n][:K] + bias) (+res) ; TN=64, K mult of 16
template<int TM, int ACT, bool BIAS, bool RES, bool TSTORE, bool PERM, bool DELTA>
__global__ void k_tgemm(const float* __restrict__ A,
                        const float* __restrict__ W,
                        const float* __restrict__ bias,
                        const float* __restrict__ res,
                        float* __restrict__ out,
                        int N, int K,
                        const float* __restrict__ dtw,
                        const float* __restrict__ dtb){
    constexpr int TN = 64, KS = 16;
    constexpr int NP = TM/32;              // f32x2 row-pairs per thread
    constexpr int AL = (TM + 63)/64;       // A loads per thread
    __shared__ float As[KS][TM+4];
    __shared__ float Bs[KS][TN+4];
    __shared__ float sdt[DELTA ? 32 : 1][8];
    int tid = threadIdx.x;
    int tx = tid & 15, ty = tid >> 4;
    int lkq = tid & 3, lm = tid >> 2;
    int m0 = blockIdx.x * TM, n0 = blockIdx.y * TN;

    u64 acc[NP][4];
    #pragma unroll
    for (int p = 0; p < NP; p++)
        #pragma unroll
        for (int j = 0; j < 4; j++) acc[p][j] = 0ull;

    float4 ra[AL]; float4 rb;
    auto loadA = [&](int m, int k)->float4{
        if (!PERM) return *(const float4*)(A + (size_t)m*K + k);
        int dir = k >> 7, c = k & 127;
        int l = stol(dir, m);
        return *(const float4*)(A + ((size_t)(dir*L + l)*CCH + c));
    };
    auto loadTile = [&](int k0){
        #pragma unroll
        for (int i = 0; i < AL; i++){
            int m = lm + i*64;
            if (m < TM) ra[i] = loadA(m0 + m, k0 + lkq*4);
        }
        int n = n0 + lm;
        rb = make_float4(0.f,0.f,0.f,0.f);
        if (n < N) rb = *(const float4*)(W + (size_t)n*K + k0 + lkq*4);
    };
    auto storeTile = [&](){
        #pragma unroll
        for (int i = 0; i < AL; i++){
            int m = lm + i*64;
            if (m < TM){
                As[lkq*4+0][m] = ra[i].x; As[lkq*4+1][m] = ra[i].y;
                As[lkq*4+2][m] = ra[i].z; As[lkq*4+3][m] = ra[i].w;
            }
        }
        Bs[lkq*4+0][lm] = rb.x; Bs[lkq*4+1][lm] = rb.y;
        Bs[lkq*4+2][lm] = rb.z; Bs[lkq*4+3][lm] = rb.w;
    };

    int NT = K / KS;
    loadTile(0);
    for (int t = 0; t < NT; t++){
        storeTile();
        __syncthreads();
        if (t + 1 < NT) loadTile((t+1)*KS);
        #pragma unroll
        for (int kk = 0; kk < KS; kk++){
            float4 bv = *(const float4*)&Bs[kk][tx*4];
            u64 bd[4];
            bd[0] = packdup(bv.x); bd[1] = packdup(bv.y);
            bd[2] = packdup(bv.z); bd[3] = packdup(bv.w);
            u64 ap[NP];
            if (TM == 32){
                ap[0] = *(const u64*)&As[kk][ty*2];
            } else if (TM == 64){
                const u64* p = (const u64*)&As[kk][ty*4];
                ap[0] = p[0]; ap[1] = p[1];
            } else {
                const u64* p0 = (const u64*)&As[kk][ty*4];
                const u64* p1 = (const u64*)&As[kk][64 + ty*4];
                ap[0] = p0[0]; ap[1] = p0[1]; ap[2] = p1[0]; ap[3] = p1[1];
            }
            #pragma unroll
            for (int p = 0; p < NP; p++)
                #pragma unroll
                for (int j = 0; j < 4; j++)
                    ffma2(acc[p][j], ap[p], bd[j]);
        }
        __syncthreads();
    }

    #pragma unroll
    for (int p = 0; p < NP; p++){
        int rbase = (TM == 32) ? ty*2
                  : (TM == 64) ? ty*4 + (p & 1)*2
                  : (p >> 1)*64 + ty*4 + (p & 1)*2;
        #pragma unroll
        for (int j = 0; j < 4; j++){
            int n = n0 + tx*4 + j;
            if (n >= N) continue;
            float lo, hi;
            unpack2(acc[p][j], lo, hi);
            #pragma unroll
            for (int half = 0; half < 2; half++){
                int mr = rbase + half;
                int m = m0 + mr;
                float v = half ? hi : lo;
                if (BIAS) v += bias[n];
                if (ACT == 1)      v = v / (1.f + __expf(-v));
                else if (ACT == 2) v = 0.5f * v * (1.f + erff(v * 0.70710678118654752f));
                else if (ACT == 3) v = (v > 20.f) ? v : log1pf(__expf(v));
                if (RES) v += res[(size_t)m*N + n];
                if (TSTORE) out[(size_t)n*L + m] = v;
                else        out[(size_t)m*N + n] = v;
                if (DELTA && n < 8) sdt[mr][n] = v;
            }
        }
    }

    if (DELTA){
        __syncthreads();
        int d = tid;
        float wr[8];
        #pragma unroll
        for (int r = 0; r < 8; r++) wr[r] = dtw[d*8 + r];
        float b = dtb[d];
        for (int tt = 0; tt < 32; tt++){
            float a = b;
            #pragma unroll
            for (int r = 0; r < 8; r++) a = fmaf(wr[r], sdt[tt][r], a);
            a = (a > 20.f) ? a : log1pf(__expf(a));
            g_delta[(size_t)(m0 + tt)*DI + d] = a;
        }
    }
}

// ---------------- K3: tiled causal depthwise conv + silu ----------------
__global__ void k_conv(const float* __restrict__ cw, const float* __restrict__ cb){
    __shared__ float sx[CTL+3][DI];
    int dir = blockIdx.y, l0 = blockIdx.x*CTL, ch = threadIdx.x;
    for (int r = 0; r < CTL+3; r++){
        int row = l0 - 3 + r;
        sx[r][ch] = (row >= 0) ? g_xz[(size_t)ptok(dir, row)*(2*DI) + ch] : 0.f;
    }
    __syncthreads();
    float w0 = cw[ch*4+0], w1 = cw[ch*4+1], w2 = cw[ch*4+2], w3 = cw[ch*4+3];
    float b = cb[ch];
    for (int i = 0; i < CTL; i++){
        float acc = b + w0*sx[i][ch] + w1*sx[i+1][ch] + w2*sx[i+2][ch] + w3*sx[i+3][ch];
        acc = acc / (1.f + __expf(-acc));
        g_xc[(size_t)(dir*L + l0 + i)*DI + ch] = acc;
    }
}

// ---------------- fused selective scan: block per (dir, d) ----------------
__global__ void __launch_bounds__(1024) k_scan(const float* __restrict__ Alog,
                                               const float* __restrict__ Dp){
    __shared__ float sP[NCHUNK][DS];
    __shared__ float sS[NCHUNK][DS];
    int bx = blockIdx.x;
    int dir = bx >> 8, d = bx & 255;
    int tid = threadIdx.x;
    int chunk = tid >> 4, n = tid & 15;
    float Av = -__expf(Alog[d*DS + n]);
    int base = dir*L + chunk*CHLEN;

    // pass A: chunk summaries
    float P = 1.f, S = 0.f;
    for (int st = 0; st < CHLEN; st++){
        int lg = base + st;
        float dl = g_delta[(size_t)lg*DI + d];
        float u  = g_xc  [(size_t)lg*DI + d];
        float Bv = g_dbl [(size_t)lg*40 + 8 + n];
        float a  = __expf(dl * Av);
        P *= a;
        S = a*S + dl*Bv*u;
    }
    sP[chunk][n] = P; sS[chunk][n] = S;
    __syncthreads();

    // Kogge-Stone inclusive scan over chunks
    #pragma unroll
    for (int off = 1; off < NCHUNK; off <<= 1){
        float pP = 1.f, pS = 0.f;
        if (chunk >= off){ pP = sP[chunk-off][n]; pS = sS[chunk-off][n]; }
        __syncthreads();
        S = fmaf(P, pS, S);
        P *= pP;
        sP[chunk][n] = P; sS[chunk][n] = S;
        __syncthreads();
    }
    float h = (chunk > 0) ? sS[chunk-1][n] : 0.f;

    // pass C: recompute with correct h0 + C-dot + D skip + silu(z) gate
    float Dv = Dp[d];
    for (int st = 0; st < CHLEN; st++){
        int lg = base + st;
        float dl = g_delta[(size_t)lg*DI + d];
        float u  = g_xc  [(size_t)lg*DI + d];
        float Bv = g_dbl [(size_t)lg*40 + 8 + n];
        float Cv = g_dbl [(size_t)lg*40 + 24 + n];
        float a  = __expf(dl * Av);
        h = a*h + dl*Bv*u;
        float p = h * Cv;
        p += __shfl_xor_sync(0xffffffffu, p, 8);
        p += __shfl_xor_sync(0xffffffffu, p, 4);
        p += __shfl_xor_sync(0xffffffffu, p, 2);
        p += __shfl_xor_sync(0xffffffffu, p, 1);
        if (n == 0){
            int l = chunk*CHLEN + st;
            float z = g_xz[(size_t)ptok(dir, l)*(2*DI) + DI + d];
            float yy = (p + u*Dv) * (z / (1.f + __expf(-z)));
            g_y[(size_t)lg*DI + d] = yy;
        }
    }
}

// ---------------- LN over channels of out_res ----------------
__device__ __forceinline__ float bsum128(float v, float* sh){
    #pragma unroll
    for (int o = 16; o; o >>= 1) v += __shfl_xor_sync(0xffffffffu, v, o);
    __syncthreads();
    if ((threadIdx.x & 31) == 0) sh[threadIdx.x >> 5] = v;
    __syncthreads();
    return sh[0] + sh[1] + sh[2] + sh[3];
}
__global__ void k_ln_res(const float* __restrict__ lnw, const float* __restrict__ lnb){
    __shared__ float sh[4];
    int s = blockIdx.x, c = threadIdx.x;
    float v   = g_resT[(size_t)s*CCH + c];
    float m   = bsum128(v, sh) * (1.f/128.f);
    float d   = v - m;
    float var = bsum128(d*d, sh) * (1.f/128.f);
    g_tok[(size_t)s*CCH + c] = d * rsqrtf(var + 1e-6f) * lnw[c] + lnb[c];
}

// ---------------- launch ----------------
extern "C" void kernel_launch(void* const* d_in, const int* in_sizes, int n_in,
                              void* d_out, int out_size){
    const float* x        = (const float*)d_in[0];
    const float* ln_w     = (const float*)d_in[1];
    const float* ln_b     = (const float*)d_in[2];
    const float* mnorm_w  = (const float*)d_in[3];
    const float* mnorm_b  = (const float*)d_in[4];
    const float* in_proj  = (const float*)d_in[5];
    const float* conv_w   = (const float*)d_in[6];
    const float* conv_b   = (const float*)d_in[7];
    const float* x_proj   = (const float*)d_in[8];
    const float* dt_proj  = (const float*)d_in[9];
    const float* dt_bias  = (const float*)d_in[10];
    const float* A_log    = (const float*)d_in[11];
    const float* D_param  = (const float*)d_in[12];
    const float* out_proj = (const float*)d_in[13];
    const float* proj_w   = (const float*)d_in[14];
    const float* proj_b   = (const float*)d_in[15];
    const float* fc1_w    = (const float*)d_in[16];
    const float* fc1_b    = (const float*)d_in[17];
    const float* fc2_w    = (const float*)d_in[18];
    const float* fc2_b    = (const float*)d_in[19];
    float* out = (float*)d_out;

    void *p_tok, *p_xz, *p_xc, *p_dbl, *p_y, *p_mo, *p_resT, *p_hid, *p_xT;
    cudaGetSymbolAddress(&p_tok,  g_tok);
    cudaGetSymbolAddress(&p_xz,   g_xz);
    cudaGetSymbolAddress(&p_xc,   g_xc);
    cudaGetSymbolAddress(&p_dbl,  g_dbl);
    cudaGetSymbolAddress(&p_y,    g_y);
    cudaGetSymbolAddress(&p_mo,   g_mo);
    cudaGetSymbolAddress(&p_resT, g_resT);
    cudaGetSymbolAddress(&p_hid,  g_hid);
    cudaGetSymbolAddress(&p_xT,   g_xT);

    // 1. fused transpose + double token LN
    k_lnx<<<L/32, 256>>>(x, ln_w, ln_b, mnorm_w, mnorm_b);
    // 2. in_proj: [4096,128]@[512,128]^T
    k_tgemm<128,0,false,false,false,false,false><<<dim3(L/128, 8), 256>>>(
        (const float*)p_tok, in_proj, nullptr, nullptr, (float*)p_xz, 512, 128, nullptr, nullptr);
    // 3. tiled causal conv + silu
    k_conv<<<dim3(L/CTL, NDIR), DI>>>(conv_w, conv_b);
    // 4. x_dbl GEMM + fused delta epilogue
    k_tgemm<32,0,false,false,false,false,true><<<dim3(LT/32, 1), 256>>>(
        (const float*)p_xc, x_proj, nullptr, nullptr, (float*)p_dbl, 40, 256, dt_proj, dt_bias);
    // 5. fused selective scan (A + combine + C)
    k_scan<<<NDIR*DI, 1024>>>(A_log, D_param);
    // 6. out_proj: [12288,256]@[128,256]^T
    k_tgemm<64,0,false,false,false,false,false><<<dim3(LT/64, 2), 256>>>(
        (const float*)p_y, out_proj, nullptr, nullptr, (float*)p_mo, 128, 256, nullptr, nullptr);
    // 7. proj(384->128) with fused 3-dir gather in A-load + bias + x residual
    k_tgemm<32,0,true,true,false,true,false><<<dim3(L/32, 2), 256>>>(
        (const float*)p_mo, proj_w, proj_b, (const float*)p_xT, (float*)p_resT, 128, 384, nullptr, nullptr);
    // 8. LN(out_res)
    k_ln_res<<<L, 128>>>(ln_w, ln_b);
    // 9. fc1 + exact GELU
    k_tgemm<128,2,true,false,false,false,false><<<dim3(L/128, 8), 256>>>(
        (const float*)p_tok, fc1_w, fc1_b, nullptr, (float*)p_hid, 512, 128, nullptr, nullptr);
    // 10. fc2 + bias + residual + transposed store to (C,D,H,W)
    k_tgemm<32,0,true,true,true,false,false><<<dim3(L/32, 2), 256>>>(
        (const float*)p_hid, fc2_w, fc2_b, (const float*)p_resT, out, 128, 512, nullptr, nullptr);
}